// round 13
// baseline (speedup 1.0000x reference)
#include <cuda_runtime.h>
#include <cstdint>

#define N_NODES 50000
#define N_EDGES 800000
#define IN_DIM  256
#define HIDDEN  128
#define OUT_DIM 64
#define NEG_SLOPE 0.1f

// Scratch (device globals: allocation-free rule)
__device__ __align__(16) float g_h0[N_NODES * HIDDEN];  // activations
__device__ __align__(16) float g_h1[N_NODES * HIDDEN];  // transformed feats (prescaled)
__device__ float g_dinv[N_NODES];
__device__ int   g_cnt[N_NODES];
__device__ int   g_fill[N_NODES];
__device__ int   g_rowptr[N_NODES + 1];
__device__ int   g_srcidx[N_EDGES];
__device__ int   g_blksum[256];
__device__ int   g_blkoff[256];
__device__ int   g_is64;

#define BUF_EXT 0
#define BUF_H0  1
#define SCAN_BLOCKS 196   // ceil(50000/256)

// ---------------------------------------------------------------------------
// tf32 helpers (single-pass: operands rounded once to tf32, fp32 accumulate)
// ---------------------------------------------------------------------------
__device__ __forceinline__ uint32_t f2tf32(float x) {
    uint32_t u;
    asm("cvt.rna.tf32.f32 %0, %1;" : "=r"(u) : "f"(x));
    return u;
}

#define MMA_TF32(D, a, b) \
    asm volatile("mma.sync.aligned.m16n8k8.row.col.f32.tf32.tf32.f32 " \
        "{%0,%1,%2,%3}, {%4,%5,%6,%7}, {%8,%9}, {%0,%1,%2,%3};" \
        : "+f"((D)[0]), "+f"((D)[1]), "+f"((D)[2]), "+f"((D)[3]) \
        : "r"((a).x), "r"((a).y), "r"((a).z), "r"((a).w), "r"((b).x), "r"((b).y))

// ---------------------------------------------------------------------------
// Init + dtype detection
// ---------------------------------------------------------------------------
__global__ void k_init() {
    int i = blockIdx.x * blockDim.x + threadIdx.x;
    if (i < N_NODES) { g_cnt[i] = 0; g_fill[i] = 0; }
    if (i == 0) g_is64 = 1;
}
// int64 edge_index with values < 50000 => every odd 32-bit word is zero.
__global__ void k_detect(const unsigned* __restrict__ e) {
    int i = blockIdx.x * blockDim.x + threadIdx.x;
    if (i < 4096) { if (e[2 * i + 1] != 0u) g_is64 = 0; }
}
__device__ __forceinline__ int edge_src(const void* ei, int e) {
    return g_is64 ? (int)((const long long*)ei)[e] : ((const int*)ei)[e];
}
__device__ __forceinline__ int edge_dst(const void* ei, int e) {
    return g_is64 ? (int)((const long long*)ei)[N_EDGES + e] : ((const int*)ei)[N_EDGES + e];
}

// ---------------------------------------------------------------------------
// CSR build: hist -> blocksum(+dinv) -> scan of block sums -> per-block scan -> place
// ---------------------------------------------------------------------------
__global__ void k_hist(const void* __restrict__ ei) {
    int e = blockIdx.x * blockDim.x + threadIdx.x;
    if (e < N_EDGES) atomicAdd(&g_cnt[edge_dst(ei, e)], 1);
}

__global__ __launch_bounds__(256) void k_blocksum() {
    __shared__ int s[256];
    int t = threadIdx.x;
    int i = blockIdx.x * 256 + t;
    int c = (i < N_NODES) ? g_cnt[i] : 0;
    if (i < N_NODES) g_dinv[i] = rsqrtf((float)c + 1.0f);   // +1 self loop
    s[t] = c; __syncthreads();
#pragma unroll
    for (int off = 128; off > 0; off >>= 1) {
        if (t < off) s[t] += s[t + off];
        __syncthreads();
    }
    if (t == 0) g_blksum[blockIdx.x] = s[0];
}

__global__ __launch_bounds__(256) void k_scanblk() {
    __shared__ int s[256];
    int t = threadIdx.x;
    int v = (t < SCAN_BLOCKS) ? g_blksum[t] : 0;
    s[t] = v; __syncthreads();
#pragma unroll
    for (int off = 1; off < 256; off <<= 1) {
        int u = (t >= off) ? s[t - off] : 0;
        __syncthreads(); s[t] += u; __syncthreads();
    }
    if (t < SCAN_BLOCKS) g_blkoff[t] = s[t] - v;            // exclusive
    if (t == 255) g_rowptr[N_NODES] = s[255];               // total
}

__global__ __launch_bounds__(256) void k_rowptr() {
    __shared__ int s[256];
    int t = threadIdx.x;
    int i = blockIdx.x * 256 + t;
    int c = (i < N_NODES) ? g_cnt[i] : 0;
    s[t] = c; __syncthreads();
#pragma unroll
    for (int off = 1; off < 256; off <<= 1) {
        int u = (t >= off) ? s[t - off] : 0;
        __syncthreads(); s[t] += u; __syncthreads();
    }
    if (i < N_NODES) g_rowptr[i] = g_blkoff[blockIdx.x] + s[t] - c;  // exclusive
}

__global__ void k_place(const void* __restrict__ ei) {
    int e = blockIdx.x * blockDim.x + threadIdx.x;
    if (e < N_EDGES) {
        int s = edge_src(ei, e), d = edge_dst(ei, e);
        g_srcidx[g_rowptr[d] + atomicAdd(&g_fill[d], 1)] = s;
    }
}

// ---------------------------------------------------------------------------
// Single-pass TF32 mma.sync GEMM: out[M=128/blk, N] = A[*, K] @ W[K, N]
// Fragment layout identical to the numerically-validated R7 kernel,
// lo-terms removed (1 MMA per tile instead of 3); KC widened to 32.
// Block 256 thr = 8 warps in 4(M) x 2(N); warp tile 32 x N/2.
// MODE 0: +bias+leaky -> g_h0 (encoder)   MODE 1: +bias -> ext (decoder)
// MODE 3: *dinv[m]    -> g_h1 (conv transform, prescaled)
// ---------------------------------------------------------------------------
template <int K, int N, int MODE, int SRC>
__global__ __launch_bounds__(256)
void k_mma_gemm(const float* __restrict__ Aext, const float* __restrict__ W,
                const float* __restrict__ bias, float* __restrict__ Oext)
{
    constexpr int KC   = 32;             // K columns per staged chunk
    constexpr int KT   = KC / 8;         // k-tiles per chunk = 4
    constexpr int NTW  = N / 16;         // n-tiles per warp (8 | 4)
    constexpr int Q4   = KC / 4;         // float4 per A row = 8
    constexpr int A_F4 = (128 * KC / 4) / 256;   // 4 float4/thread (A)
    constexpr int B_F4 = (KC * N / 4) / 256;     // 4 (N=128) | 2 (N=64)

    __shared__ uint32_t sA[128 * KC];    // 16 KB
    __shared__ uint32_t sB[KC * N];      // 16 KB (N=128) | 8 KB

    const float* A   = (SRC == BUF_H0) ? g_h0 : Aext;
    float*       out = (MODE == 0) ? g_h0 : ((MODE == 3) ? g_h1 : Oext);

    const int tid    = threadIdx.x;
    const int wid    = tid >> 5;
    const int lane   = tid & 31;
    const int warp_m = wid >> 1;         // 0..3
    const int warp_n = wid & 1;          // 0..1
    const int gq     = lane >> 2;        // 0..7
    const int tq     = lane & 3;         // 0..3
    const int m0     = blockIdx.x * 128;

    float acc[2][NTW][4];
#pragma unroll
    for (int mt = 0; mt < 2; mt++)
#pragma unroll
        for (int nt = 0; nt < NTW; nt++)
#pragma unroll
            for (int j = 0; j < 4; j++) acc[mt][nt][j] = 0.0f;

    for (int kt0 = 0; kt0 < K; kt0 += KC) {
        // ---- stage A chunk: 128 rows x 32 cols, tf32, fragment order ----
#pragma unroll
        for (int j = 0; j < A_F4; j++) {
            int f = tid + j * 256;           // float4 index
            int r = f / Q4, q = f % Q4;
            int m = m0 + r;
            float4 v = (m < N_NODES) ? *(const float4*)&A[(size_t)m * K + kt0 + q * 4]
                                     : make_float4(0.f, 0.f, 0.f, 0.f);
            float vv[4] = {v.x, v.y, v.z, v.w};
            int rb = r >> 4, rr = r & 15;
#pragma unroll
            for (int c2 = 0; c2 < 4; c2++) {
                int kl = q * 4 + c2;
                int kt = kl >> 3, t8 = kl & 7;
                int reg = ((rr >> 3) & 1) | ((t8 >> 2) << 1);
                int ln  = ((rr & 7) << 2) | (t8 & 3);
                sA[((rb * KT + kt) * 32 + ln) * 4 + reg] = f2tf32(vv[c2]);
            }
        }
        // ---- stage B chunk: B[k][n] = W[kt0+k][n] ----
#pragma unroll
        for (int j = 0; j < B_F4; j++) {
            int f = tid + j * 256;
            int kl = f / (N / 4), q = f % (N / 4);
            float4 v = *(const float4*)&W[(size_t)(kt0 + kl) * N + q * 4];
            float vv[4] = {v.x, v.y, v.z, v.w};
            int kt = kl >> 3, t8 = kl & 7;
            int reg = (t8 >> 2) & 1;
#pragma unroll
            for (int c2 = 0; c2 < 4; c2++) {
                int n = q * 4 + c2;
                int nt = n >> 3, g = n & 7;
                int ln  = (g << 2) | (t8 & 3);
                sB[((nt * KT + kt) * 32 + ln) * 2 + reg] = f2tf32(vv[c2]);
            }
        }
        __syncthreads();

        // ---- MMA over fragments (layout validated in R7) ----
#pragma unroll
        for (int kt = 0; kt < KT; kt++) {
            uint4 ah[2];
#pragma unroll
            for (int mt = 0; mt < 2; mt++) {
                int rb = warp_m * 2 + mt;
                ah[mt] = *(const uint4*)&sA[((rb * KT + kt) * 32 + lane) * 4];
            }
#pragma unroll
            for (int ntl = 0; ntl < NTW; ntl++) {
                int nt = warp_n * NTW + ntl;
                uint2 bh = *(const uint2*)&sB[((nt * KT + kt) * 32 + lane) * 2];
#pragma unroll
                for (int mt = 0; mt < 2; mt++)
                    MMA_TF32(acc[mt][ntl], ah[mt], bh);
            }
        }
        __syncthreads();
    }

    // ---- epilogue: D frag c0/c1 -> row gq cols 2tq,2tq+1; c2/c3 -> row gq+8 ----
#pragma unroll
    for (int mt = 0; mt < 2; mt++) {
        int r0 = m0 + warp_m * 32 + mt * 16 + gq;
        int r1 = r0 + 8;
        float s0 = 1.0f, s1 = 1.0f;
        if (MODE == 3) {
            if (r0 < N_NODES) s0 = g_dinv[r0];
            if (r1 < N_NODES) s1 = g_dinv[r1];
        }
#pragma unroll
        for (int ntl = 0; ntl < NTW; ntl++) {
            int c0 = (warp_n * NTW + ntl) * 8 + 2 * tq;
            float b0 = 0.f, b1 = 0.f;
            if (MODE == 0 || MODE == 1) { b0 = bias[c0]; b1 = bias[c0 + 1]; }
            float d0 = acc[mt][ntl][0] + b0, d1 = acc[mt][ntl][1] + b1;
            float d2 = acc[mt][ntl][2] + b0, d3 = acc[mt][ntl][3] + b1;
            if (MODE == 0) {
                d0 = d0 > 0.f ? d0 : NEG_SLOPE * d0;
                d1 = d1 > 0.f ? d1 : NEG_SLOPE * d1;
                d2 = d2 > 0.f ? d2 : NEG_SLOPE * d2;
                d3 = d3 > 0.f ? d3 : NEG_SLOPE * d3;
            }
            if (MODE == 3) { d0 *= s0; d1 *= s0; d2 *= s1; d3 *= s1; }
            if (r0 < N_NODES) *(float2*)&out[(size_t)r0 * N + c0] = make_float2(d0, d1);
            if (r1 < N_NODES) *(float2*)&out[(size_t)r1 * N + c0] = make_float2(d2, d3);
        }
    }
}

// ---------------------------------------------------------------------------
// Aggregation gather: one warp per dst node; h1 prescaled by dinv.
// h0[d] = leaky(dinv[d]*(h1'[d] + sum h1'[src]) + bias)
// ---------------------------------------------------------------------------
__global__ __launch_bounds__(256)
void k_gather(const float* __restrict__ bias)
{
    int d    = (blockIdx.x * blockDim.x + threadIdx.x) >> 5;
    int lane = threadIdx.x & 31;
    if (d >= N_NODES) return;

    float dd  = g_dinv[d];
    int   beg = g_rowptr[d], end = g_rowptr[d + 1];

    float4 acc = *(const float4*)&g_h1[(size_t)d * HIDDEN + lane * 4];  // self

    for (int j0 = beg; j0 < end; j0 += 32) {
        int n = min(32, end - j0);
        int myidx = (j0 + lane < end) ? g_srcidx[j0 + lane] : 0;
        for (int c = 0; c < n; c++) {
            int s = __shfl_sync(0xffffffffu, myidx, c);
            float4 u = *(const float4*)&g_h1[(size_t)s * HIDDEN + lane * 4];
            acc.x += u.x; acc.y += u.y; acc.z += u.z; acc.w += u.w;
        }
    }

    int c = lane * 4;
    acc.x = acc.x * dd + bias[c];     acc.y = acc.y * dd + bias[c + 1];
    acc.z = acc.z * dd + bias[c + 2]; acc.w = acc.w * dd + bias[c + 3];
    acc.x = acc.x > 0.f ? acc.x : NEG_SLOPE * acc.x;
    acc.y = acc.y > 0.f ? acc.y : NEG_SLOPE * acc.y;
    acc.z = acc.z > 0.f ? acc.z : NEG_SLOPE * acc.z;
    acc.w = acc.w > 0.f ? acc.w : NEG_SLOPE * acc.w;
    *(float4*)&g_h0[(size_t)d * HIDDEN + c] = acc;
}

// ---------------------------------------------------------------------------
// Launch
// ---------------------------------------------------------------------------
extern "C" void kernel_launch(void* const* d_in, const int* in_sizes, int n_in,
                              void* d_out, int out_size)
{
    const float* x      = (const float*)d_in[0];
    const void*  ei     = d_in[1];                 // int32 or int64, detected
    const float* enc_W  = (const float*)d_in[2];
    const float* enc_b  = (const float*)d_in[3];
    const float* conv_W = (const float*)d_in[4];   // [2,128,128]
    const float* conv_b = (const float*)d_in[5];   // [2,128]
    const float* dec_W  = (const float*)d_in[6];
    const float* dec_b  = (const float*)d_in[7];
    float*       out    = (float*)d_out;

    const int nodeBlocks = (N_NODES + 255) / 256;       // 196
    const int edgeBlocks = (N_EDGES + 255) / 256;
    const int mmaBlocks  = (N_NODES + 127) / 128;       // 391
    const int gathBlocks = (N_NODES * 32 + 255) / 256;

    k_init<<<nodeBlocks, 256>>>();
    k_detect<<<16, 256>>>((const unsigned*)ei);
    k_hist<<<edgeBlocks, 256>>>(ei);
    k_blocksum<<<SCAN_BLOCKS, 256>>>();
    k_scanblk<<<1, 256>>>();
    k_rowptr<<<SCAN_BLOCKS, 256>>>();
    k_place<<<edgeBlocks, 256>>>(ei);

    // encoder: h0 = leaky(x @ enc_W + enc_b)
    k_mma_gemm<IN_DIM, HIDDEN, 0, BUF_EXT><<<mmaBlocks, 256>>>(x, enc_W, enc_b, nullptr);

    for (int l = 0; l < 2; l++) {
        const float* W = conv_W + (size_t)l * HIDDEN * HIDDEN;
        const float* b = conv_b + (size_t)l * HIDDEN;
        // g_h1 = (h0 @ W) * dinv   (prescaled transform)
        k_mma_gemm<HIDDEN, HIDDEN, 3, BUF_H0><<<mmaBlocks, 256>>>(nullptr, W, nullptr, nullptr);
        // h0 = leaky(dinv * (h1'[self] + sum h1'[src]) + b)
        k_gather<<<gathBlocks, 256>>>(b);
    }

    // decoder: out = h0 @ dec_W + dec_b
    k_mma_gemm<HIDDEN, OUT_DIM, 1, BUF_H0><<<mmaBlocks, 256>>>(nullptr, dec_W, dec_b, out);
}

// round 14
// speedup vs baseline: 1.1849x; 1.1849x over previous
#include <cuda_runtime.h>
#include <cuda_bf16.h>
#include <cstdint>

#define N_NODES 50000
#define N_EDGES 800000
#define IN_DIM  256
#define HIDDEN  128
#define OUT_DIM 64
#define NEG_SLOPE 0.1f

// Scratch (device globals: allocation-free rule)
__device__ __align__(16) float    g_h0[N_NODES * HIDDEN];   // activations (fp32)
__device__ __align__(16) unsigned g_h1b[N_NODES * 64];      // prescaled feats, bf16x2 (12.8MB)
__device__ float g_dinv[N_NODES];
__device__ int   g_cnt[N_NODES];
__device__ int   g_fill[N_NODES];
__device__ int   g_rowptr[N_NODES + 1];
__device__ int   g_srcidx[N_EDGES];
__device__ int   g_blksum[256];
__device__ int   g_blkoff[256];
__device__ int   g_is64;

#define BUF_EXT 0
#define BUF_H0  1
#define SCAN_BLOCKS 196   // ceil(50000/256)

// ---------------------------------------------------------------------------
// Init + dtype detection
// ---------------------------------------------------------------------------
__global__ void k_init() {
    int i = blockIdx.x * blockDim.x + threadIdx.x;
    if (i < N_NODES) { g_cnt[i] = 0; g_fill[i] = 0; }
    if (i == 0) g_is64 = 1;
}
// int64 edge_index with values < 50000 => every odd 32-bit word is zero.
__global__ void k_detect(const unsigned* __restrict__ e) {
    int i = blockIdx.x * blockDim.x + threadIdx.x;
    if (i < 4096) { if (e[2 * i + 1] != 0u) g_is64 = 0; }
}
__device__ __forceinline__ int edge_src(const void* ei, int e) {
    return g_is64 ? (int)((const long long*)ei)[e] : ((const int*)ei)[e];
}
__device__ __forceinline__ int edge_dst(const void* ei, int e) {
    return g_is64 ? (int)((const long long*)ei)[N_EDGES + e] : ((const int*)ei)[N_EDGES + e];
}

// ---------------------------------------------------------------------------
// CSR build: hist -> blocksum(+dinv) -> scan of block sums -> per-block scan -> place
// ---------------------------------------------------------------------------
__global__ void k_hist(const void* __restrict__ ei) {
    int e = blockIdx.x * blockDim.x + threadIdx.x;
    if (e < N_EDGES) atomicAdd(&g_cnt[edge_dst(ei, e)], 1);
}

__global__ __launch_bounds__(256) void k_blocksum() {
    __shared__ int s[256];
    int t = threadIdx.x;
    int i = blockIdx.x * 256 + t;
    int c = (i < N_NODES) ? g_cnt[i] : 0;
    if (i < N_NODES) g_dinv[i] = rsqrtf((float)c + 1.0f);   // +1 self loop
    s[t] = c; __syncthreads();
#pragma unroll
    for (int off = 128; off > 0; off >>= 1) {
        if (t < off) s[t] += s[t + off];
        __syncthreads();
    }
    if (t == 0) g_blksum[blockIdx.x] = s[0];
}

__global__ __launch_bounds__(256) void k_scanblk() {
    __shared__ int s[256];
    int t = threadIdx.x;
    int v = (t < SCAN_BLOCKS) ? g_blksum[t] : 0;
    s[t] = v; __syncthreads();
#pragma unroll
    for (int off = 1; off < 256; off <<= 1) {
        int u = (t >= off) ? s[t - off] : 0;
        __syncthreads(); s[t] += u; __syncthreads();
    }
    if (t < SCAN_BLOCKS) g_blkoff[t] = s[t] - v;            // exclusive
    if (t == 255) g_rowptr[N_NODES] = s[255];               // total
}

__global__ __launch_bounds__(256) void k_rowptr() {
    __shared__ int s[256];
    int t = threadIdx.x;
    int i = blockIdx.x * 256 + t;
    int c = (i < N_NODES) ? g_cnt[i] : 0;
    s[t] = c; __syncthreads();
#pragma unroll
    for (int off = 1; off < 256; off <<= 1) {
        int u = (t >= off) ? s[t - off] : 0;
        __syncthreads(); s[t] += u; __syncthreads();
    }
    if (i < N_NODES) g_rowptr[i] = g_blkoff[blockIdx.x] + s[t] - c;  // exclusive
}

__global__ void k_place(const void* __restrict__ ei) {
    int e = blockIdx.x * blockDim.x + threadIdx.x;
    if (e < N_EDGES) {
        int s = edge_src(ei, e), d = edge_dst(ei, e);
        g_srcidx[g_rowptr[d] + atomicAdd(&g_fill[d], 1)] = s;
    }
}

// ---------------------------------------------------------------------------
// Tiled fp32 GEMM:  out[M,C] = A[M,K] @ W[K,C]
// TM=64, TK=64, 256 threads; k-unrolled x4 with float4 A broadcasts:
//   per 4 k-steps: 4 LDS.128 (W) + RPT LDS.128 (A) + 16*RPT FFMA  (91.5% FMA)
// MODE 0: +bias, leaky  (encoder: A=ext, out=g_h0)
// MODE 1: +bias         (decoder: A=g_h0, out=ext)
// MODE 3: *dinv[m] -> bf16 pairs into g_h1b (conv transform, prescaled)
// ---------------------------------------------------------------------------
template <int K, int C, int MODE, int SRC>
__global__ __launch_bounds__(256)
void k_gemm(const float* __restrict__ Aext, const float* __restrict__ W,
            const float* __restrict__ bias, float* __restrict__ Oext)
{
    constexpr int TM = 64, TK = 64;
    constexpr int CG = C / 4;          // col groups (float4 wide): 32 | 16
    constexpr int RG = 256 / CG;       // row groups: 8 | 16
    constexpr int RPT = TM / RG;       // rows per thread: 8 | 4

    __shared__ float xs[TM][TK];       // 16 KB
    __shared__ float ws[TK][C];        // 32 KB (C=128) | 16 KB

    const float* A   = (SRC == BUF_H0) ? g_h0 : Aext;
    float*       out = (MODE == 0) ? g_h0 : Oext;

    const int m0  = blockIdx.x * TM;
    const int tid = threadIdx.x;
    const int cg  = tid % CG;
    const int rg  = tid / CG;

    float acc[RPT][4];
#pragma unroll
    for (int r = 0; r < RPT; r++)
#pragma unroll
        for (int j = 0; j < 4; j++) acc[r][j] = 0.0f;

    for (int kt = 0; kt < K; kt += TK) {
        // stage A tile (zero-pad past M): 1024 float4, 4 per thread
#pragma unroll
        for (int i = tid; i < TM * TK / 4; i += 256) {
            int row = (i * 4) / TK, col = (i * 4) % TK;
            int m = m0 + row;
            float4 v = make_float4(0.f, 0.f, 0.f, 0.f);
            if (m < N_NODES)
                v = *(const float4*)&A[(size_t)m * K + kt + col];
            *(float4*)&xs[row][col] = v;
        }
        // stage W tile
#pragma unroll
        for (int i = tid; i < TK * C / 4; i += 256) {
            int row = (i * 4) / C, col = (i * 4) % C;
            *(float4*)&ws[row][col] = *(const float4*)&W[(size_t)(kt + row) * C + col];
        }
        __syncthreads();

#pragma unroll
        for (int k = 0; k < TK; k += 4) {
            float4 wv0 = *(const float4*)&ws[k + 0][cg * 4];
            float4 wv1 = *(const float4*)&ws[k + 1][cg * 4];
            float4 wv2 = *(const float4*)&ws[k + 2][cg * 4];
            float4 wv3 = *(const float4*)&ws[k + 3][cg * 4];
#pragma unroll
            for (int r = 0; r < RPT; r++) {
                float4 a4 = *(const float4*)&xs[rg * RPT + r][k];  // broadcast LDS.128
                acc[r][0] += a4.x * wv0.x; acc[r][1] += a4.x * wv0.y;
                acc[r][2] += a4.x * wv0.z; acc[r][3] += a4.x * wv0.w;
                acc[r][0] += a4.y * wv1.x; acc[r][1] += a4.y * wv1.y;
                acc[r][2] += a4.y * wv1.z; acc[r][3] += a4.y * wv1.w;
                acc[r][0] += a4.z * wv2.x; acc[r][1] += a4.z * wv2.y;
                acc[r][2] += a4.z * wv2.z; acc[r][3] += a4.z * wv2.w;
                acc[r][0] += a4.w * wv3.x; acc[r][1] += a4.w * wv3.y;
                acc[r][2] += a4.w * wv3.z; acc[r][3] += a4.w * wv3.w;
            }
        }
        __syncthreads();
    }

#pragma unroll
    for (int r = 0; r < RPT; r++) {
        int m = m0 + rg * RPT + r;
        if (m >= N_NODES) continue;
        int c = cg * 4;
        float4 v = make_float4(acc[r][0], acc[r][1], acc[r][2], acc[r][3]);
        if (MODE == 0 || MODE == 1) {
            v.x += bias[c]; v.y += bias[c + 1]; v.z += bias[c + 2]; v.w += bias[c + 3];
        }
        if (MODE == 0) {
            v.x = v.x > 0.f ? v.x : NEG_SLOPE * v.x;
            v.y = v.y > 0.f ? v.y : NEG_SLOPE * v.y;
            v.z = v.z > 0.f ? v.z : NEG_SLOPE * v.z;
            v.w = v.w > 0.f ? v.w : NEG_SLOPE * v.w;
        }
        if (MODE == 3) {
            float di = g_dinv[m];
            __nv_bfloat162 p0 = __floats2bfloat162_rn(v.x * di, v.y * di);
            __nv_bfloat162 p1 = __floats2bfloat162_rn(v.z * di, v.w * di);
            uint2 u;
            u.x = *(unsigned*)&p0;
            u.y = *(unsigned*)&p1;
            *(uint2*)&g_h1b[(size_t)m * 64 + cg * 2] = u;   // cols 4cg.. as bf16x2
        } else {
            *(float4*)&out[(size_t)m * C + c] = v;
        }
    }
}

// ---------------------------------------------------------------------------
// Aggregation gather: one warp per dst node; h1' stored bf16 (prescaled).
// h0[d] = leaky(dinv[d]*(h1'[d] + sum h1'[src]) + bias)   fp32 accumulate
// ---------------------------------------------------------------------------
__global__ __launch_bounds__(256)
void k_gather(const float* __restrict__ bias)
{
    int d    = (blockIdx.x * blockDim.x + threadIdx.x) >> 5;
    int lane = threadIdx.x & 31;
    if (d >= N_NODES) return;

    float dd  = g_dinv[d];
    int   beg = g_rowptr[d], end = g_rowptr[d + 1];

    // self term
    uint2 su = *(const uint2*)&g_h1b[(size_t)d * 64 + lane * 2];
    float2 f0 = __bfloat1622float2(*(__nv_bfloat162*)&su.x);
    float2 f1 = __bfloat1622float2(*(__nv_bfloat162*)&su.y);
    float4 acc = make_float4(f0.x, f0.y, f1.x, f1.y);

    for (int j0 = beg; j0 < end; j0 += 32) {
        int n = min(32, end - j0);
        int myidx = (j0 + lane < end) ? g_srcidx[j0 + lane] : 0;
        for (int c = 0; c < n; c++) {
            int s = __shfl_sync(0xffffffffu, myidx, c);
            uint2 u = *(const uint2*)&g_h1b[(size_t)s * 64 + lane * 2];
            float2 a = __bfloat1622float2(*(__nv_bfloat162*)&u.x);
            float2 b = __bfloat1622float2(*(__nv_bfloat162*)&u.y);
            acc.x += a.x; acc.y += a.y; acc.z += b.x; acc.w += b.y;
        }
    }

    int c = lane * 4;
    acc.x = acc.x * dd + bias[c];     acc.y = acc.y * dd + bias[c + 1];
    acc.z = acc.z * dd + bias[c + 2]; acc.w = acc.w * dd + bias[c + 3];
    acc.x = acc.x > 0.f ? acc.x : NEG_SLOPE * acc.x;
    acc.y = acc.y > 0.f ? acc.y : NEG_SLOPE * acc.y;
    acc.z = acc.z > 0.f ? acc.z : NEG_SLOPE * acc.z;
    acc.w = acc.w > 0.f ? acc.w : NEG_SLOPE * acc.w;
    *(float4*)&g_h0[(size_t)d * HIDDEN + c] = acc;
}

// ---------------------------------------------------------------------------
// Launch
// ---------------------------------------------------------------------------
extern "C" void kernel_launch(void* const* d_in, const int* in_sizes, int n_in,
                              void* d_out, int out_size)
{
    const float* x      = (const float*)d_in[0];
    const void*  ei     = d_in[1];                 // int32 or int64, detected
    const float* enc_W  = (const float*)d_in[2];
    const float* enc_b  = (const float*)d_in[3];
    const float* conv_W = (const float*)d_in[4];   // [2,128,128]
    const float* conv_b = (const float*)d_in[5];   // [2,128]
    const float* dec_W  = (const float*)d_in[6];
    const float* dec_b  = (const float*)d_in[7];
    float*       out    = (float*)d_out;

    const int nodeBlocks = (N_NODES + 255) / 256;       // 196
    const int edgeBlocks = (N_EDGES + 255) / 256;
    const int gemmBlocks = (N_NODES + 63) / 64;         // 782
    const int gathBlocks = (N_NODES * 32 + 255) / 256;

    k_init<<<nodeBlocks, 256>>>();
    k_detect<<<16, 256>>>((const unsigned*)ei);
    k_hist<<<edgeBlocks, 256>>>(ei);
    k_blocksum<<<SCAN_BLOCKS, 256>>>();
    k_scanblk<<<1, 256>>>();
    k_rowptr<<<SCAN_BLOCKS, 256>>>();
    k_place<<<edgeBlocks, 256>>>(ei);

    // encoder: h0 = leaky(x @ enc_W + enc_b)
    k_gemm<IN_DIM, HIDDEN, 0, BUF_EXT><<<gemmBlocks, 256>>>(x, enc_W, enc_b, nullptr);

    for (int l = 0; l < 2; l++) {
        const float* W = conv_W + (size_t)l * HIDDEN * HIDDEN;
        const float* b = conv_b + (size_t)l * HIDDEN;
        // g_h1b = bf16((h0 @ W) * dinv)   (prescaled transform)
        k_gemm<HIDDEN, HIDDEN, 3, BUF_H0><<<gemmBlocks, 256>>>(nullptr, W, nullptr, nullptr);
        // h0 = leaky(dinv * (h1'[self] + sum h1'[src]) + b)
        k_gather<<<gathBlocks, 256>>>(b);
    }

    // decoder: out = h0 @ dec_W + dec_b
    k_gemm<HIDDEN, OUT_DIM, 1, BUF_H0><<<gemmBlocks, 256>>>(nullptr, dec_W, dec_b, out);
}

// round 15
// speedup vs baseline: 1.2656x; 1.0681x over previous
#include <cuda_runtime.h>
#include <cuda_bf16.h>
#include <cstdint>

#define N_NODES 50000
#define N_EDGES 800000
#define IN_DIM  256
#define HIDDEN  128
#define OUT_DIM 64
#define NEG_SLOPE 0.1f

// Scratch (device globals: allocation-free rule)
__device__ __align__(16) float    g_h0[N_NODES * HIDDEN];   // activations (fp32)
__device__ __align__(16) unsigned g_h1b[N_NODES * 64];      // prescaled feats, bf16x2
__device__ float g_dinv[N_NODES];
__device__ int   g_cnt[N_NODES];
__device__ int   g_fill[N_NODES];      // seeded with rowptr by k_rowptr
__device__ int   g_rowptr[N_NODES + 1];
__device__ int   g_srcidx[N_EDGES];
__device__ int   g_blksum[256];
__device__ int   g_blkoff[256];
__device__ int   g_is64;

#define BUF_EXT 0
#define BUF_H0  1
#define SCAN_BLOCKS 196    // ceil(50000/256)
#define GEMM_BLOCKS 782    // ceil(50000/64)
#define EDGE_XBLK   256    // extra blocks fused onto GEMM launches

// ---------------------------------------------------------------------------
// Init + dtype detection
// ---------------------------------------------------------------------------
__global__ void k_init() {
    int i = blockIdx.x * blockDim.x + threadIdx.x;
    if (i < N_NODES) g_cnt[i] = 0;
    if (i == 0) g_is64 = 1;
}
// int64 edge_index with values < 50000 => every odd 32-bit word is zero.
__global__ void k_detect(const unsigned* __restrict__ e) {
    int i = blockIdx.x * blockDim.x + threadIdx.x;
    if (i < 4096) { if (e[2 * i + 1] != 0u) g_is64 = 0; }
}

// ---------------------------------------------------------------------------
// CSR scan: blocksum(+dinv) -> scan of block sums -> per-block scan(+fill seed)
// ---------------------------------------------------------------------------
__global__ __launch_bounds__(256) void k_blocksum() {
    __shared__ int s[256];
    int t = threadIdx.x;
    int i = blockIdx.x * 256 + t;
    int c = (i < N_NODES) ? g_cnt[i] : 0;
    if (i < N_NODES) g_dinv[i] = rsqrtf((float)c + 1.0f);   // +1 self loop
    s[t] = c; __syncthreads();
#pragma unroll
    for (int off = 128; off > 0; off >>= 1) {
        if (t < off) s[t] += s[t + off];
        __syncthreads();
    }
    if (t == 0) g_blksum[blockIdx.x] = s[0];
}

__global__ __launch_bounds__(256) void k_scanblk() {
    __shared__ int s[256];
    int t = threadIdx.x;
    int v = (t < SCAN_BLOCKS) ? g_blksum[t] : 0;
    s[t] = v; __syncthreads();
#pragma unroll
    for (int off = 1; off < 256; off <<= 1) {
        int u = (t >= off) ? s[t - off] : 0;
        __syncthreads(); s[t] += u; __syncthreads();
    }
    if (t < SCAN_BLOCKS) g_blkoff[t] = s[t] - v;            // exclusive
    if (t == 255) g_rowptr[N_NODES] = s[255];               // total
}

__global__ __launch_bounds__(256) void k_rowptr() {
    __shared__ int s[256];
    int t = threadIdx.x;
    int i = blockIdx.x * 256 + t;
    int c = (i < N_NODES) ? g_cnt[i] : 0;
    s[t] = c; __syncthreads();
#pragma unroll
    for (int off = 1; off < 256; off <<= 1) {
        int u = (t >= off) ? s[t - off] : 0;
        __syncthreads(); s[t] += u; __syncthreads();
    }
    if (i < N_NODES) {
        int rp = g_blkoff[blockIdx.x] + s[t] - c;           // exclusive
        g_rowptr[i] = rp;
        g_fill[i]   = rp;                                   // seed write cursor
    }
}

// ---------------------------------------------------------------------------
// Tiled fp32 GEMM with fused edge work in extra blocks:
//   blocks [0, GEMM_BLOCKS)            : GEMM (TM=64, TK=64, k-unroll x4)
//   blocks [GEMM_BLOCKS, +EDGE_XBLK)   : PAR==1 hist | PAR==2 place
// MODE 0: +bias, leaky  (encoder: A=ext, out=g_h0)
// MODE 1: +bias         (decoder: A=g_h0, out=ext)
// MODE 3: *dinv[m] -> bf16 pairs into g_h1b (conv transform, prescaled)
// ---------------------------------------------------------------------------
template <int K, int C, int MODE, int SRC, int PAR>
__global__ __launch_bounds__(256)
void k_gemm(const float* __restrict__ Aext, const float* __restrict__ W,
            const float* __restrict__ bias, float* __restrict__ Oext,
            const void* __restrict__ ei)
{
    constexpr int TM = 64, TK = 64;
    constexpr int CG = C / 4;
    constexpr int RG = 256 / CG;
    constexpr int RPT = TM / RG;

    __shared__ float xs[TM][TK];       // 16 KB
    __shared__ float ws[TK][C];        // 32 KB (C=128) | 16 KB

    if (PAR != 0 && blockIdx.x >= GEMM_BLOCKS) {
        // -------- fused edge pass (grid-stride) --------
        const int t0 = (blockIdx.x - GEMM_BLOCKS) * 256 + threadIdx.x;
        const int stride = EDGE_XBLK * 256;
        const int is64 = g_is64;
        if (PAR == 1) {            // histogram of dst
            for (int e = t0; e < N_EDGES; e += stride) {
                int d = is64 ? (int)((const long long*)ei)[N_EDGES + e]
                             : ((const int*)ei)[N_EDGES + e];
                atomicAdd(&g_cnt[d], 1);
            }
        } else {                   // CSR placement (g_fill pre-seeded w/ rowptr)
            for (int e = t0; e < N_EDGES; e += stride) {
                int s, d;
                if (is64) {
                    s = (int)((const long long*)ei)[e];
                    d = (int)((const long long*)ei)[N_EDGES + e];
                } else {
                    s = ((const int*)ei)[e];
                    d = ((const int*)ei)[N_EDGES + e];
                }
                g_srcidx[atomicAdd(&g_fill[d], 1)] = s;
            }
        }
        return;
    }

    // -------- GEMM --------
    const float* A   = (SRC == BUF_H0) ? g_h0 : Aext;
    float*       out = (MODE == 0) ? g_h0 : Oext;

    const int m0  = blockIdx.x * TM;
    const int tid = threadIdx.x;
    const int cg  = tid % CG;
    const int rg  = tid / CG;

    float acc[RPT][4];
#pragma unroll
    for (int r = 0; r < RPT; r++)
#pragma unroll
        for (int j = 0; j < 4; j++) acc[r][j] = 0.0f;

    for (int kt = 0; kt < K; kt += TK) {
#pragma unroll
        for (int i = tid; i < TM * TK / 4; i += 256) {
            int row = (i * 4) / TK, col = (i * 4) % TK;
            int m = m0 + row;
            float4 v = make_float4(0.f, 0.f, 0.f, 0.f);
            if (m < N_NODES)
                v = *(const float4*)&A[(size_t)m * K + kt + col];
            *(float4*)&xs[row][col] = v;
        }
#pragma unroll
        for (int i = tid; i < TK * C / 4; i += 256) {
            int row = (i * 4) / C, col = (i * 4) % C;
            *(float4*)&ws[row][col] = *(const float4*)&W[(size_t)(kt + row) * C + col];
        }
        __syncthreads();

#pragma unroll
        for (int k = 0; k < TK; k += 4) {
            float4 wv0 = *(const float4*)&ws[k + 0][cg * 4];
            float4 wv1 = *(const float4*)&ws[k + 1][cg * 4];
            float4 wv2 = *(const float4*)&ws[k + 2][cg * 4];
            float4 wv3 = *(const float4*)&ws[k + 3][cg * 4];
#pragma unroll
            for (int r = 0; r < RPT; r++) {
                float4 a4 = *(const float4*)&xs[rg * RPT + r][k];  // broadcast LDS.128
                acc[r][0] += a4.x * wv0.x; acc[r][1] += a4.x * wv0.y;
                acc[r][2] += a4.x * wv0.z; acc[r][3] += a4.x * wv0.w;
                acc[r][0] += a4.y * wv1.x; acc[r][1] += a4.y * wv1.y;
                acc[r][2] += a4.y * wv1.z; acc[r][3] += a4.y * wv1.w;
                acc[r][0] += a4.z * wv2.x; acc[r][1] += a4.z * wv2.y;
                acc[r][2] += a4.z * wv2.z; acc[r][3] += a4.z * wv2.w;
                acc[r][0] += a4.w * wv3.x; acc[r][1] += a4.w * wv3.y;
                acc[r][2] += a4.w * wv3.z; acc[r][3] += a4.w * wv3.w;
            }
        }
        __syncthreads();
    }

#pragma unroll
    for (int r = 0; r < RPT; r++) {
        int m = m0 + rg * RPT + r;
        if (m >= N_NODES) continue;
        int c = cg * 4;
        float4 v = make_float4(acc[r][0], acc[r][1], acc[r][2], acc[r][3]);
        if (MODE == 0 || MODE == 1) {
            v.x += bias[c]; v.y += bias[c + 1]; v.z += bias[c + 2]; v.w += bias[c + 3];
        }
        if (MODE == 0) {
            v.x = v.x > 0.f ? v.x : NEG_SLOPE * v.x;
            v.y = v.y > 0.f ? v.y : NEG_SLOPE * v.y;
            v.z = v.z > 0.f ? v.z : NEG_SLOPE * v.z;
            v.w = v.w > 0.f ? v.w : NEG_SLOPE * v.w;
        }
        if (MODE == 3) {
            float di = g_dinv[m];
            __nv_bfloat162 p0 = __floats2bfloat162_rn(v.x * di, v.y * di);
            __nv_bfloat162 p1 = __floats2bfloat162_rn(v.z * di, v.w * di);
            uint2 u;
            u.x = *(unsigned*)&p0;
            u.y = *(unsigned*)&p1;
            *(uint2*)&g_h1b[(size_t)m * 64 + cg * 2] = u;
        } else {
            *(float4*)&out[(size_t)m * C + c] = v;
        }
    }
}

// ---------------------------------------------------------------------------
// Aggregation gather: one warp per dst node; h1' stored bf16 (prescaled).
// h0[d] = leaky(dinv[d]*(h1'[d] + sum h1'[src]) + bias)   fp32 accumulate
// ---------------------------------------------------------------------------
__global__ __launch_bounds__(256)
void k_gather(const float* __restrict__ bias)
{
    int d    = (blockIdx.x * blockDim.x + threadIdx.x) >> 5;
    int lane = threadIdx.x & 31;
    if (d >= N_NODES) return;

    float dd  = g_dinv[d];
    int   beg = g_rowptr[d], end = g_rowptr[d + 1];

    uint2 su = *(const uint2*)&g_h1b[(size_t)d * 64 + lane * 2];
    float2 f0 = __bfloat1622float2(*(__nv_bfloat162*)&su.x);
    float2 f1 = __bfloat1622float2(*(__nv_bfloat162*)&su.y);
    float4 acc = make_float4(f0.x, f0.y, f1.x, f1.y);

    for (int j0 = beg; j0 < end; j0 += 32) {
        int n = min(32, end - j0);
        int myidx = (j0 + lane < end) ? g_srcidx[j0 + lane] : 0;
        for (int c = 0; c < n; c++) {
            int s = __shfl_sync(0xffffffffu, myidx, c);
            uint2 u = *(const uint2*)&g_h1b[(size_t)s * 64 + lane * 2];
            float2 a = __bfloat1622float2(*(__nv_bfloat162*)&u.x);
            float2 b = __bfloat1622float2(*(__nv_bfloat162*)&u.y);
            acc.x += a.x; acc.y += a.y; acc.z += b.x; acc.w += b.y;
        }
    }

    int c = lane * 4;
    acc.x = acc.x * dd + bias[c];     acc.y = acc.y * dd + bias[c + 1];
    acc.z = acc.z * dd + bias[c + 2]; acc.w = acc.w * dd + bias[c + 3];
    acc.x = acc.x > 0.f ? acc.x : NEG_SLOPE * acc.x;
    acc.y = acc.y > 0.f ? acc.y : NEG_SLOPE * acc.y;
    acc.z = acc.z > 0.f ? acc.z : NEG_SLOPE * acc.z;
    acc.w = acc.w > 0.f ? acc.w : NEG_SLOPE * acc.w;
    *(float4*)&g_h0[(size_t)d * HIDDEN + c] = acc;
}

// ---------------------------------------------------------------------------
// Launch
// ---------------------------------------------------------------------------
extern "C" void kernel_launch(void* const* d_in, const int* in_sizes, int n_in,
                              void* d_out, int out_size)
{
    const float* x      = (const float*)d_in[0];
    const void*  ei     = d_in[1];                 // int32 or int64, detected
    const float* enc_W  = (const float*)d_in[2];
    const float* enc_b  = (const float*)d_in[3];
    const float* conv_W = (const float*)d_in[4];   // [2,128,128]
    const float* conv_b = (const float*)d_in[5];   // [2,128]
    const float* dec_W  = (const float*)d_in[6];
    const float* dec_b  = (const float*)d_in[7];
    float*       out    = (float*)d_out;

    const int nodeBlocks = (N_NODES + 255) / 256;       // 196
    const int gathBlocks = (N_NODES * 32 + 255) / 256;

    k_init<<<nodeBlocks, 256>>>();
    k_detect<<<16, 256>>>((const unsigned*)ei);

    // encoder GEMM  ∪  dst-histogram (fused, independent)
    k_gemm<IN_DIM, HIDDEN, 0, BUF_EXT, 1>
        <<<GEMM_BLOCKS + EDGE_XBLK, 256>>>(x, enc_W, enc_b, nullptr, ei);

    k_blocksum<<<SCAN_BLOCKS, 256>>>();
    k_scanblk<<<1, 256>>>();
    k_rowptr<<<SCAN_BLOCKS, 256>>>();                   // also seeds g_fill

    // conv layer 0: transform GEMM  ∪  CSR placement (fused, independent)
    {
        const float* W = conv_W;
        const float* b = conv_b;
        k_gemm<HIDDEN, HIDDEN, 3, BUF_H0, 2>
            <<<GEMM_BLOCKS + EDGE_XBLK, 256>>>(nullptr, W, nullptr, nullptr, ei);
        k_gather<<<gathBlocks, 256>>>(b);
    }
    // conv layer 1
    {
        const float* W = conv_W + (size_t)HIDDEN * HIDDEN;
        const float* b = conv_b + HIDDEN;
        k_gemm<HIDDEN, HIDDEN, 3, BUF_H0, 0>
            <<<GEMM_BLOCKS, 256>>>(nullptr, W, nullptr, nullptr, nullptr);
        k_gather<<<gathBlocks, 256>>>(b);
    }

    // decoder: out = h0 @ dec_W + dec_b
    k_gemm<HIDDEN, OUT_DIM, 1, BUF_H0, 0>
        <<<GEMM_BLOCKS, 256>>>(nullptr, dec_W, dec_b, out, nullptr);
}